// round 3
// baseline (speedup 1.0000x reference)
#include <cuda_runtime.h>

#define NN 100000
#define NE 1600000
#define C  64

// ---- device scratch (no allocation allowed) ----
__device__ int   g_deg[NN];
__device__ int   g_off[NN];
__device__ int   g_cur[NN];
__device__ float g_dinv[NN];
__device__ int   g_srcs[NE];
__device__ float g_h1[(size_t)NN * C];
__device__ float g_h2[(size_t)NN * C];
__device__ float g_agg[(size_t)NN * C];
__device__ float g_WlT[3][C * C];   // transposed: WlT[k*64+c] = Wl[c*64+k]
__device__ float g_WrT[3][C * C];

// ---------------- CSR build ----------------
__global__ void zero_deg_k() {
    int i = blockIdx.x * blockDim.x + threadIdx.x;
    if (i < NN) g_deg[i] = 0;
}

// edge_index is int32 on device (JAX default x64-disabled downcasts int64).
__global__ void count_k(const int* __restrict__ ei) {
    int e = blockIdx.x * blockDim.x + threadIdx.x;
    if (e < NE) {
        int dst = ei[NE + e];
        if ((unsigned)dst < (unsigned)NN) atomicAdd(&g_deg[dst], 1);
    }
}

// single-block exclusive scan over g_deg -> g_off, g_cur; also deg_inv
__global__ void scan_k() {
    __shared__ int wsum[32];
    __shared__ int carry;
    int tid  = threadIdx.x;
    int lane = tid & 31;
    int wid  = tid >> 5;
    if (tid == 0) carry = 0;
    __syncthreads();
    for (int base = 0; base < NN; base += 1024) {
        int i = base + tid;
        int v = (i < NN) ? g_deg[i] : 0;
        int x = v;
        #pragma unroll
        for (int o = 1; o < 32; o <<= 1) {
            int y = __shfl_up_sync(0xffffffffu, x, o);
            if (lane >= o) x += y;
        }
        if (lane == 31) wsum[wid] = x;
        __syncthreads();
        if (wid == 0) {
            int w = wsum[lane];
            #pragma unroll
            for (int o = 1; o < 32; o <<= 1) {
                int y = __shfl_up_sync(0xffffffffu, w, o);
                if (lane >= o) w += y;
            }
            wsum[lane] = w;
        }
        __syncthreads();
        int pre = (wid > 0) ? wsum[wid - 1] : 0;
        int c0  = carry;
        int excl = c0 + pre + x - v;
        if (i < NN) {
            g_off[i]  = excl;
            g_cur[i]  = excl;
            g_dinv[i] = 1.0f / (float)((v > 0) ? v : 1);
        }
        __syncthreads();
        if (tid == 0) carry = c0 + wsum[31];
        __syncthreads();
    }
}

__global__ void fill_k(const int* __restrict__ ei) {
    int e = blockIdx.x * blockDim.x + threadIdx.x;
    if (e < NE) {
        int src = ei[e];
        int dst = ei[NE + e];
        if ((unsigned)dst < (unsigned)NN && (unsigned)src < (unsigned)NN) {
            int p = atomicAdd(&g_cur[dst], 1);
            if ((unsigned)p < (unsigned)NE) g_srcs[p] = src;
        }
    }
}

// ---------------- weight transpose (once per launch, tiny) ----------------
__global__ void wtrans_k(const float* __restrict__ Wl0, const float* __restrict__ Wr0,
                         const float* __restrict__ Wl1, const float* __restrict__ Wr1,
                         const float* __restrict__ Wl2, const float* __restrict__ Wr2) {
    int l = blockIdx.x;  // 0..2
    const float* Wl = (l == 0) ? Wl0 : (l == 1) ? Wl1 : Wl2;
    const float* Wr = (l == 0) ? Wr0 : (l == 1) ? Wr1 : Wr2;
    for (int idx = threadIdx.x; idx < C * C; idx += blockDim.x) {
        int k = idx >> 6, c = idx & 63;
        g_WlT[l][idx] = Wl[c * C + k];   // write coalesced, read gathered (tiny)
        g_WrT[l][idx] = Wr[c * C + k];
    }
}

// ---------------- mean aggregation: warp per node ----------------
// insel: 0 = x (param), 1 = g_h1, 2 = g_h2
__global__ void agg_k(const float* __restrict__ x, int insel) {
    const float* in = (insel == 0) ? x : (insel == 1) ? g_h1 : g_h2;
    int warp = (blockIdx.x * blockDim.x + threadIdx.x) >> 5;
    int lane = threadIdx.x & 31;
    if (warp >= NN) return;
    int s = g_off[warp];
    int d = g_deg[warp];
    float ax = 0.f, ay = 0.f;
    int i = 0;
    for (; i + 4 <= d; i += 4) {
        int u0 = g_srcs[s + i + 0];
        int u1 = g_srcs[s + i + 1];
        int u2 = g_srcs[s + i + 2];
        int u3 = g_srcs[s + i + 3];
        float2 t0 = ((const float2*)(in + (size_t)u0 * C))[lane];
        float2 t1 = ((const float2*)(in + (size_t)u1 * C))[lane];
        float2 t2 = ((const float2*)(in + (size_t)u2 * C))[lane];
        float2 t3 = ((const float2*)(in + (size_t)u3 * C))[lane];
        ax += (t0.x + t1.x) + (t2.x + t3.x);
        ay += (t0.y + t1.y) + (t2.y + t3.y);
    }
    for (; i < d; i++) {
        int u = g_srcs[s + i];
        float2 t = ((const float2*)(in + (size_t)u * C))[lane];
        ax += t.x;
        ay += t.y;
    }
    float di = g_dinv[warp];
    float2 r;
    r.x = ax * di;
    r.y = ay * di;
    ((float2*)(g_agg + (size_t)warp * C))[lane] = r;
}

// ---------------- fused dual-GEMM transform ----------------
// out[v][c] = sum_k agg[v][k]*Wl[c][k] + bl[c] + sum_k h[v][k]*Wr[c][k], optional relu
// 32 nodes x 64 channels per block, 256 threads, 2x4 register tile per thread.
// Static smem exactly 48KB: WlT[64][64] + WrT[64][64] + A[64k][32n] + H[64k][32n].
__global__ void __launch_bounds__(256) xform_k(const float* __restrict__ x,
                                               const float* __restrict__ bl,
                                               float* __restrict__ outp,
                                               int layer, int insel, int outsel,
                                               int relu) {
    __shared__ float sWl[C * C];      // [k][c] 16KB
    __shared__ float sWr[C * C];      // [k][c] 16KB
    __shared__ float sA[C * 32];      // [k][n] 8KB
    __shared__ float sH[C * 32];      // [k][n] 8KB

    const float* hin = (insel == 0) ? x : (insel == 1) ? g_h1 : g_h2;
    float* outb = (outsel == 1) ? g_h1 : (outsel == 2) ? g_h2 : outp;

    int tid = threadIdx.x;
    int v0  = blockIdx.x * 32;

    // stage transposed weights: pure coalesced copy, conflict-free
    const float* wlT = g_WlT[layer];
    const float* wrT = g_WrT[layer];
    #pragma unroll
    for (int it = 0; it < 16; it++) {
        int idx = it * 256 + tid;
        sWl[idx] = wlT[idx];
        sWr[idx] = wrT[idx];
    }

    // stage 32 node rows of agg and h, K-major (sA[k][n]); store banks = n -> conflict-free
    #pragma unroll
    for (int it = 0; it < 2; it++) {
        int idx = it * 256 + tid;          // 0..511
        int n = idx & 31, q = idx >> 5;    // q = 0..15 (float4 quad)
        int v = v0 + n;
        float4 a = make_float4(0.f, 0.f, 0.f, 0.f), h = a;
        if (v < NN) {
            a = ((const float4*)(g_agg + (size_t)v * C))[q];
            h = ((const float4*)(hin   + (size_t)v * C))[q];
        }
        sA[(q * 4 + 0) * 32 + n] = a.x;
        sA[(q * 4 + 1) * 32 + n] = a.y;
        sA[(q * 4 + 2) * 32 + n] = a.z;
        sA[(q * 4 + 3) * 32 + n] = a.w;
        sH[(q * 4 + 0) * 32 + n] = h.x;
        sH[(q * 4 + 1) * 32 + n] = h.y;
        sH[(q * 4 + 2) * 32 + n] = h.z;
        sH[(q * 4 + 3) * 32 + n] = h.w;
    }
    __syncthreads();

    int tc = tid & 15;    // channels tc*4 .. tc*4+3
    int tg = tid >> 4;    // node group: nodes tg*2, tg*2+1
    int n0 = tg * 2;

    float4 bias = ((const float4*)bl)[tc];   // global, L2-cached, once per thread
    float acc[2][4];
    #pragma unroll
    for (int j = 0; j < 2; j++) {
        acc[j][0] = bias.x; acc[j][1] = bias.y; acc[j][2] = bias.z; acc[j][3] = bias.w;
    }

    #pragma unroll 8
    for (int k = 0; k < C; k++) {
        float4 wl = *(const float4*)(sWl + k * C + tc * 4);
        float4 wr = *(const float4*)(sWr + k * C + tc * 4);
        float a0 = sA[k * 32 + n0];
        float a1 = sA[k * 32 + n0 + 1];
        float h0 = sH[k * 32 + n0];
        float h1 = sH[k * 32 + n0 + 1];
        acc[0][0] += a0 * wl.x + h0 * wr.x;
        acc[0][1] += a0 * wl.y + h0 * wr.y;
        acc[0][2] += a0 * wl.z + h0 * wr.z;
        acc[0][3] += a0 * wl.w + h0 * wr.w;
        acc[1][0] += a1 * wl.x + h1 * wr.x;
        acc[1][1] += a1 * wl.y + h1 * wr.y;
        acc[1][2] += a1 * wl.z + h1 * wr.z;
        acc[1][3] += a1 * wl.w + h1 * wr.w;
    }

    #pragma unroll
    for (int j = 0; j < 2; j++) {
        int v = v0 + n0 + j;
        if (v < NN) {
            float4 r;
            r.x = acc[j][0]; r.y = acc[j][1]; r.z = acc[j][2]; r.w = acc[j][3];
            if (relu) {
                r.x = fmaxf(r.x, 0.f); r.y = fmaxf(r.y, 0.f);
                r.z = fmaxf(r.z, 0.f); r.w = fmaxf(r.w, 0.f);
            }
            *(float4*)(outb + (size_t)v * C + tc * 4) = r;
        }
    }
}

extern "C" void kernel_launch(void* const* d_in, const int* in_sizes, int n_in,
                              void* d_out, int out_size) {
    const float* x   = (const float*)d_in[0];
    const int*   ei  = (const int*)d_in[1];    // int32! (JAX x64-disabled)
    const float* Wl0 = (const float*)d_in[2];
    const float* bl0 = (const float*)d_in[3];
    const float* Wr0 = (const float*)d_in[4];
    const float* Wl1 = (const float*)d_in[5];
    const float* bl1 = (const float*)d_in[6];
    const float* Wr1 = (const float*)d_in[7];
    const float* Wl2 = (const float*)d_in[8];
    const float* bl2 = (const float*)d_in[9];
    const float* Wr2 = (const float*)d_in[10];
    float* out = (float*)d_out;

    // CSR build + weight transpose
    zero_deg_k<<<(NN + 255) / 256, 256>>>();
    count_k<<<(NE + 255) / 256, 256>>>(ei);
    scan_k<<<1, 1024>>>();
    fill_k<<<(NE + 255) / 256, 256>>>(ei);
    wtrans_k<<<3, 256>>>(Wl0, Wr0, Wl1, Wr1, Wl2, Wr2);

    const int AGG_BLOCKS = (NN + 7) / 8;    // 8 warps (nodes) per 256-thread block
    const int XF_BLOCKS  = (NN + 31) / 32;  // 32 nodes per block

    // layer 0: x -> g_h1 (relu)
    agg_k<<<AGG_BLOCKS, 256>>>(x, 0);
    xform_k<<<XF_BLOCKS, 256>>>(x, bl0, out, 0, 0, 1, 1);
    // layer 1: g_h1 -> g_h2 (relu)
    agg_k<<<AGG_BLOCKS, 256>>>(x, 1);
    xform_k<<<XF_BLOCKS, 256>>>(x, bl1, out, 1, 1, 2, 1);
    // layer 2: g_h2 -> out (no relu)
    agg_k<<<AGG_BLOCKS, 256>>>(x, 2);
    xform_k<<<XF_BLOCKS, 256>>>(x, bl2, out, 2, 2, 0, 0);
}